// round 15
// baseline (speedup 1.0000x reference)
#include <cuda_runtime.h>
#include <cuda_bf16.h>
#include <cuda_fp16.h>
#include <cstdint>

#define T_LEN 8192
#define BATCH 2
#define CDIM 1024
#define NHEAD 16
#define HDIM 64
#define WINSZ 256
#define NWIN_TOT 64
#define NTOK (BATCH * T_LEN)     // 16384

// ---------------- scratch ----------------------------------------------------
__device__ __half g_XH[(size_t)NTOK * CDIM];        // x, fp16
__device__ __half g_AOH[(size_t)NTOK * CDIM];       // attn out, fp16
__device__ __half g_WH[4][(size_t)CDIM * CDIM];     // weights, fp16
__device__ __half g_QH[(size_t)NTOK * NHEAD * 64];  // rope'd Q fp16 [tok*16+h][64]
__device__ __half g_KH[(size_t)NTOK * NHEAD * 64];
__device__ __half g_VH[(size_t)NTOK * NHEAD * 64];
__device__ unsigned char g_attend[NWIN_TOT * 512];
__device__ int g_maskmode;

// ---------------- helpers ------------------------------------------------------
__device__ __forceinline__ uint32_t smem_u32(const void* p) {
    uint32_t a;
    asm("{ .reg .u64 t; cvta.to.shared.u64 t, %1; cvt.u32.u64 %0, t; }" : "=r"(a) : "l"(p));
    return a;
}
__device__ __forceinline__ void cp16(uint32_t dst, const void* src) {
    asm volatile("cp.async.cg.shared.global [%0], [%1], 16;" :: "r"(dst), "l"(src));
}
__device__ __forceinline__ void cp16z(uint32_t dst, const void* src, uint32_t sz) {
    asm volatile("cp.async.cg.shared.global [%0], [%1], 16, %2;" :: "r"(dst), "l"(src), "r"(sz));
}
__device__ __forceinline__ void cp_commit() { asm volatile("cp.async.commit_group;"); }
template <int N> __device__ __forceinline__ void cp_wait() {
    asm volatile("cp.async.wait_group %0;" :: "n"(N));
}
__device__ __forceinline__ void ldsm4(uint32_t (&r)[4], uint32_t addr) {
    asm volatile("ldmatrix.sync.aligned.m8n8.x4.shared.b16 {%0,%1,%2,%3}, [%4];"
                 : "=r"(r[0]), "=r"(r[1]), "=r"(r[2]), "=r"(r[3]) : "r"(addr));
}
__device__ __forceinline__ void ldsm4t(uint32_t (&r)[4], uint32_t addr) {
    asm volatile("ldmatrix.sync.aligned.m8n8.x4.trans.shared.b16 {%0,%1,%2,%3}, [%4];"
                 : "=r"(r[0]), "=r"(r[1]), "=r"(r[2]), "=r"(r[3]) : "r"(addr));
}
__device__ __forceinline__ void mma16816h(float (&c)[4], const uint32_t (&a)[4],
                                          uint32_t b0, uint32_t b1) {
    asm volatile(
        "mma.sync.aligned.m16n8k16.row.col.f32.f16.f16.f32 "
        "{%0,%1,%2,%3}, {%4,%5,%6,%7}, {%8,%9}, {%0,%1,%2,%3};"
        : "+f"(c[0]), "+f"(c[1]), "+f"(c[2]), "+f"(c[3])
        : "r"(a[0]), "r"(a[1]), "r"(a[2]), "r"(a[3]), "r"(b0), "r"(b1));
}
__device__ __forceinline__ uint32_t ex2_f16x2(float t0, float t1) {
    __half2 h = __floats2half2_rn(t0, t1);
    uint32_t r;
    asm("ex2.approx.f16x2 %0, %1;" : "=r"(r) : "r"(*(uint32_t*)&h));
    return r;
}

// ---------------- fp32 -> fp16 conversion passes --------------------------------
__global__ void to_half(const float* __restrict__ in, __half* __restrict__ out) {
    int i = blockIdx.x * blockDim.x + threadIdx.x;
    float4 v = ((const float4*)in)[i];
    __half2 h01 = __floats2half2_rn(v.x, v.y);
    __half2 h23 = __floats2half2_rn(v.z, v.w);
    ((__half2*)out)[2 * i] = h01;
    ((__half2*)out)[2 * i + 1] = h23;
}
__global__ void to_half_w(const float* __restrict__ w0, const float* __restrict__ w1,
                          const float* __restrict__ w2, const float* __restrict__ w3,
                          __half* __restrict__ out) {
    int z = blockIdx.y;
    const float* in = (z == 0) ? w0 : ((z == 1) ? w1 : ((z == 2) ? w2 : w3));
    __half* o = out + (size_t)z * CDIM * CDIM;
    int i = blockIdx.x * blockDim.x + threadIdx.x;
    float4 v = ((const float4*)in)[i];
    __half2 h01 = __floats2half2_rn(v.x, v.y);
    __half2 h23 = __floats2half2_rn(v.z, v.w);
    ((__half2*)o)[2 * i] = h01;
    ((__half2*)o)[2 * i + 1] = h23;
}

// ---------------- fp16 GEMM, 128x128 CTA tile, 256 threads (R10-proven) --------
#define GK 1024
#define CH 16
#define NST 3
#define STAGE_B 32768             // A 16KB + B 16KB
#define SMEM_GEMM (NST * STAGE_B)

__device__ __forceinline__ void load_chunk(uint32_t stage, const __half* Arow,
                                           const __half* Brow, int kbase, int tid) {
#pragma unroll
    for (int i = 0; i < 4; i++) {
        int f = tid + i * 256;
        int rr = f >> 3, seg = f & 7;
        uint32_t off = rr * 128 + seg * 16;
        uint32_t sw = off ^ ((off >> 3) & 0x70);
        cp16(stage + sw, Arow + (size_t)rr * GK + kbase + seg * 8);
        cp16(stage + 16384 + sw, Brow + (size_t)rr * GK + kbase + seg * 8);
    }
}

__device__ __forceinline__ void gemm_mainloop(char* dsm, const __half* Arow,
        const __half* Brow, int tid, int lane, int m0, int n0,
        float (&acc)[2][8][4]) {
    uint32_t sbase = smem_u32(dsm);

    int rA = m0 + (lane & 7) + ((lane >> 3) & 1) * 8;
    int ksegA = lane >> 4;
    int swA = rA & 7;
    int rB = n0 + (lane & 7) + ((lane >> 4) << 3);
    int ksegB = (lane >> 3) & 1;
    int swB = rB & 7;

    uint32_t aRowOff[2], bRowOff[4];
#pragma unroll
    for (int mi = 0; mi < 2; mi++) aRowOff[mi] = (uint32_t)(rA + mi * 16) * 128;
#pragma unroll
    for (int g = 0; g < 4; g++) bRowOff[g] = 16384u + (uint32_t)(rB + g * 16) * 128;

#pragma unroll
    for (int mi = 0; mi < 2; mi++)
#pragma unroll
        for (int nt = 0; nt < 8; nt++)
#pragma unroll
            for (int j = 0; j < 4; j++) acc[mi][nt][j] = 0.0f;

    load_chunk(sbase, Arow, Brow, 0, tid);
    cp_commit();
    load_chunk(sbase + STAGE_B, Arow, Brow, 64, tid);
    cp_commit();

    for (int c = 0; c < CH; c++) {
        if (c + 2 < CH) load_chunk(sbase + ((c + 2) % NST) * STAGE_B, Arow, Brow,
                                   (c + 2) * 64, tid);
        cp_commit();
        cp_wait<2>();
        __syncthreads();

        uint32_t stg = sbase + (c % NST) * STAGE_B;
#pragma unroll
        for (int step = 0; step < 4; step++) {
            uint32_t a[2][4];
#pragma unroll
            for (int mi = 0; mi < 2; mi++)
                ldsm4(a[mi], stg + aRowOff[mi] + ((uint32_t)((step * 2 + ksegA) ^ swA) << 4));
            uint32_t b[4][4];
#pragma unroll
            for (int g = 0; g < 4; g++)
                ldsm4(b[g], stg + bRowOff[g] + ((uint32_t)((step * 2 + ksegB) ^ swB) << 4));
#pragma unroll
            for (int mi = 0; mi < 2; mi++)
#pragma unroll
                for (int nt = 0; nt < 8; nt++)
                    mma16816h(acc[mi][nt], a[mi], b[nt >> 1][(nt & 1) * 2],
                              b[nt >> 1][(nt & 1) * 2 + 1]);
        }
        __syncthreads();
    }
}

// ---------------- fused QKV GEMM: bias + (rope) + fp16 store -------------------
__global__ void __launch_bounds__(256) gemm_qkv(const __half* __restrict__ A,
        const __half* __restrict__ WHbase,
        const float* __restrict__ bq, const float* __restrict__ bk,
        const float* __restrict__ bv,
        const float* __restrict__ cosT, const float* __restrict__ sinT,
        __half* __restrict__ QH, __half* __restrict__ KH, __half* __restrict__ VH) {
    extern __shared__ char dsm[];
    int which = blockIdx.z;
    const __half* W = WHbase + (size_t)which * CDIM * CDIM;
    const float* bias = (which == 0) ? bq : ((which == 1) ? bk : bv);
    __half* outH = (which == 0) ? QH : ((which == 1) ? KH : VH);

    int tid = threadIdx.x;
    int wid = tid >> 5, lane = tid & 31;
    int row0 = blockIdx.y * 128;
    int col0 = blockIdx.x * 128;
    int m0 = (wid & 3) * 32;
    int n0 = (wid >> 2) * 64;

    float acc[2][8][4];
    gemm_mainloop(dsm, A + (size_t)row0 * GK, W + (size_t)col0 * GK,
                  tid, lane, m0, n0, acc);

    int g = lane >> 2;
    int cl = (lane & 3) * 2;
    int hh = (col0 + n0) >> 6;

#pragma unroll
    for (int mi = 0; mi < 2; mi++)
#pragma unroll
        for (int nt = 0; nt < 8; nt++) {
            int gcol = col0 + n0 + nt * 8 + cl;
            float b0 = bias[gcol], b1 = bias[gcol + 1];
            acc[mi][nt][0] += b0; acc[mi][nt][1] += b1;
            acc[mi][nt][2] += b0; acc[mi][nt][3] += b1;
        }

    if (which < 2) {   // rope on Q, K
#pragma unroll
        for (int mi = 0; mi < 2; mi++) {
            int r0 = row0 + m0 + mi * 16 + g;
            int pos0 = r0 & (T_LEN - 1);
            const float* c0 = cosT + (size_t)pos0 * HDIM;
            const float* s0 = sinT + (size_t)pos0 * HDIM;
            const float* c1 = c0 + 8 * HDIM;
            const float* s1 = s0 + 8 * HDIM;
#pragma unroll
            for (int nt = 0; nt < 4; nt++) {
                int d = nt * 8 + cl;
                float2 cA0 = *(const float2*)(c0 + d), sA0 = *(const float2*)(s0 + d);
                float2 cB0 = *(const float2*)(c0 + d + 32), sB0 = *(const float2*)(s0 + d + 32);
                float2 cA1 = *(const float2*)(c1 + d), sA1 = *(const float2*)(s1 + d);
                float2 cB1 = *(const float2*)(c1 + d + 32), sB1 = *(const float2*)(s1 + d + 32);
                float a, b;
                a = acc[mi][nt][0]; b = acc[mi][nt + 4][0];
                acc[mi][nt][0]     = a * cA0.x - b * sA0.x;
                acc[mi][nt + 4][0] = b * cB0.x + a * sB0.x;
                a = acc[mi][nt][1]; b = acc[mi][nt + 4][1];
                acc[mi][nt][1]     = a * cA0.y - b * sA0.y;
                acc[mi][nt + 4][1] = b * cB0.y + a * sB0.y;
                a = acc[mi][nt][2]; b = acc[mi][nt + 4][2];
                acc[mi][nt][2]     = a * cA1.x - b * sA1.x;
                acc[mi][nt + 4][2] = b * cB1.x + a * sB1.x;
                a = acc[mi][nt][3]; b = acc[mi][nt + 4][3];
                acc[mi][nt][3]     = a * cA1.y - b * sA1.y;
                acc[mi][nt + 4][3] = b * cB1.y + a * sB1.y;
            }
        }
    }

#pragma unroll
    for (int mi = 0; mi < 2; mi++) {
        int r0 = row0 + m0 + mi * 16 + g;
        __half* o0 = outH + ((size_t)r0 * NHEAD + hh) * 64;
        __half* o1 = outH + ((size_t)(r0 + 8) * NHEAD + hh) * 64;
#pragma unroll
        for (int nt = 0; nt < 8; nt++) {
            int d = nt * 8 + cl;
            __half2 v0 = __floats2half2_rn(acc[mi][nt][0], acc[mi][nt][1]);
            __half2 v1 = __floats2half2_rn(acc[mi][nt][2], acc[mi][nt][3]);
            *(__half2*)(o0 + d) = v0;
            *(__half2*)(o1 + d) = v1;
        }
    }
}

// ---------------- O-projection GEMM: fp32 out + bias ---------------------------
__global__ void __launch_bounds__(256) gemm_f16(const __half* __restrict__ A,
        const __half* __restrict__ Bw, const float* __restrict__ bias,
        float* __restrict__ C) {
    extern __shared__ char dsm[];
    int tid = threadIdx.x;
    int wid = tid >> 5, lane = tid & 31;
    int row0 = blockIdx.y * 128;
    int col0 = blockIdx.x * 128;
    int m0 = (wid & 3) * 32;
    int n0 = (wid >> 2) * 64;

    float acc[2][8][4];
    gemm_mainloop(dsm, A + (size_t)row0 * GK, Bw + (size_t)col0 * GK,
                  tid, lane, m0, n0, acc);

    int g = lane >> 2;
    int cl = (lane & 3) * 2;
#pragma unroll
    for (int mi = 0; mi < 2; mi++) {
#pragma unroll
        for (int nt = 0; nt < 8; nt++) {
            int gcol = col0 + n0 + nt * 8 + cl;
            float b0 = bias[gcol], b1 = bias[gcol + 1];
            int r0 = row0 + m0 + mi * 16 + g;
            float2 v0 = make_float2(acc[mi][nt][0] + b0, acc[mi][nt][1] + b1);
            float2 v1 = make_float2(acc[mi][nt][2] + b0, acc[mi][nt][3] + b1);
            *(float2*)(C + (size_t)r0 * CDIM + gcol) = v0;
            *(float2*)(C + (size_t)(r0 + 8) * CDIM + gcol) = v1;
        }
    }
}

// ---------------- mask dtype detection + attend mask -------------------------
__global__ void detect_mask(const unsigned int* __restrict__ m) {
    __shared__ int okf, oki;
    if (threadIdx.x == 0) { okf = 1; oki = 1; }
    __syncthreads();
    for (int i = threadIdx.x; i < 4096; i += blockDim.x) {
        unsigned int w = m[i];
        if (w != 0u && w != 0x3f800000u) okf = 0;
        if (w > 1u) oki = 0;
    }
    __syncthreads();
    if (threadIdx.x == 0) g_maskmode = okf ? 2 : (oki ? 1 : 0);
}

__global__ void build_attend(const void* __restrict__ pm) {
    int w = blockIdx.x;
    int b = w >> 5;
    int wi = w & 31;
    int j = threadIdx.x;
    int p = wi * WINSZ - 128 + j;
    int attend = 1;
    if ((unsigned)p < (unsigned)T_LEN) {
        int mm = g_maskmode;
        size_t im = (size_t)b * T_LEN + p;
        int v;
        if (mm == 0)      v = ((const unsigned char*)pm)[im] != 0;
        else if (mm == 1) v = ((const int*)pm)[im] != 0;
        else              v = ((const float*)pm)[im] != 0.0f;
        attend = !v;
    }
    __shared__ int allb;
    if (j == 0) allb = 1;
    __syncthreads();
    if (!attend) allb = 0;
    __syncthreads();
    if (j == 0 && allb) attend = 0;
    g_attend[w * 512 + j] = (unsigned char)attend;
}

// ---------------- tensor-core windowed attention (fp16, ex2.f16x2, 3-stage) ---
#define ATT_STG 32768
#define ATT_BIAS (32768 + 3 * 16384)   // 81920
#define SMEM_ATTN (1024 + ATT_BIAS + 256)
#define LOG2E8 0.18033688011112042f    // 0.125 * log2(e)

__device__ __forceinline__ void load_kv_chunk(uint32_t stg, const __half* KH,
        const __half* VH, int b, int h, int p0, int tid) {
#pragma unroll
    for (int i = 0; i < 2; i++) {
        int f = tid + i * 256;
        int r = f >> 3, seg = f & 7;
        int p = p0 + r;
        uint32_t ok = ((unsigned)p < (unsigned)T_LEN) ? 16u : 0u;
        int pc = (p < 0) ? 0 : ((p >= T_LEN) ? (T_LEN - 1) : p);
        const __half* kk = KH + (((size_t)(b * T_LEN + pc) * NHEAD + h) << 6) + seg * 8;
        const __half* vv = VH + (((size_t)(b * T_LEN + pc) * NHEAD + h) << 6) + seg * 8;
        uint32_t sw = (uint32_t)r * 128 + (uint32_t)(((seg ^ (r & 7)) << 4));
        cp16z(stg + sw, kk, ok);
        cp16z(stg + 8192 + sw, vv, ok);
    }
}

__global__ void __launch_bounds__(256) attn_mma(
        const __half* __restrict__ QH, const __half* __restrict__ KH,
        const __half* __restrict__ VH, __half* __restrict__ AO) {
    extern __shared__ char sm[];
    char* smA = (char*)(((uintptr_t)sm + 1023) & ~(uintptr_t)1023);
    uint32_t sb = smem_u32(smA);
    float* biasP = (float*)(smA + ATT_BIAS);

    int h = blockIdx.x, w = blockIdx.y;
    int b = w >> 5, wi = w & 31;
    int tid = threadIdx.x, wid = tid >> 5, lane = tid & 31;
    int w0 = wid * 32;

    int rA = (lane & 7) + ((lane >> 3) & 1) * 8;
    int ksegA = lane >> 4;
    int rB = (lane & 7) + ((lane >> 4) << 3);
    int ksegB = (lane >> 3) & 1;
    int krV = (lane & 7) + ((lane >> 4) << 3);
    int nsegV = (lane >> 3) & 1;

#pragma unroll
    for (int i = 0; i < 8; i++) {
        int f = tid + i * 256;
        int r = f >> 3, seg = f & 7;
        const __half* q = QH + (((size_t)(b * T_LEN + wi * 256 + r) * NHEAD + h) << 6)
                          + seg * 8;
        uint32_t sw = (uint32_t)r * 128 + (uint32_t)(((seg ^ (r & 7)) << 4));
        cp16(sb + sw, q);
    }
    load_kv_chunk(sb + ATT_STG, KH, VH, b, h, wi * 256 - 128, tid);
    cp_commit();
    load_kv_chunk(sb + ATT_STG + 16384, KH, VH, b, h, wi * 256 - 64, tid);
    cp_commit();

    float O[2][8][4];
#pragma unroll
    for (int mi = 0; mi < 2; mi++)
#pragma unroll
        for (int nt = 0; nt < 8; nt++)
#pragma unroll
            for (int j = 0; j < 4; j++) O[mi][nt][j] = 0.0f;
    float lrow[4] = {0.f, 0.f, 0.f, 0.f};

    for (int c = 0; c < 8; c++) {
        // prefetch chunk c+2 into ring slot (c+2)%3 (its previous user c-1 is done)
        if (c + 2 < 8)
            load_kv_chunk(sb + ATT_STG + (uint32_t)((c + 2) % 3) * 16384u, KH, VH, b, h,
                          wi * 256 - 128 + (c + 2) * 64, tid);
        cp_commit();            // uniform commit count
        cp_wait<2>();           // chunk c resident
        if (tid < 64)
            biasP[tid] = g_attend[w * 512 + c * 64 + tid] ? 0.0f : -30000.0f;
        __syncthreads();

        uint32_t stg = sb + ATT_STG + (uint32_t)(c % 3) * 16384u;

        // ---- S = Q K^T
        float S[2][8][4];
#pragma unroll
        for (int mi = 0; mi < 2; mi++)
#pragma unroll
            for (int nt = 0; nt < 8; nt++)
#pragma unroll
                for (int j = 0; j < 4; j++) S[mi][nt][j] = 0.0f;

#pragma unroll
        for (int step = 0; step < 4; step++) {
            uint32_t kb[4][4];
#pragma unroll
            for (int g = 0; g < 4; g++) {
                int row = g * 16 + rB;
                ldsm4(kb[g], stg + (uint32_t)row * 128
                      + (uint32_t)(((step * 2 + ksegB) ^ (row & 7)) << 4));
            }
#pragma unroll
            for (int mi = 0; mi < 2; mi++) {
                int rowQ = w0 + mi * 16 + rA;
                uint32_t qf[4];
                ldsm4(qf, sb + (uint32_t)rowQ * 128
                      + (uint32_t)(((step * 2 + ksegA) ^ (rowQ & 7)) << 4));
#pragma unroll
                for (int nt = 0; nt < 8; nt++)
                    mma16816h(S[mi][nt], qf, kb[nt >> 1][(nt & 1) * 2],
                              kb[nt >> 1][(nt & 1) * 2 + 1]);
            }
        }

        // ---- P = ex2(S*0.125*log2e + bias) in fp16x2; lrow via HADD2 pairing
        float2 bias[8];
#pragma unroll
        for (int nt = 0; nt < 8; nt++)
            bias[nt] = *(float2*)&biasP[nt * 8 + 2 * (lane & 3)];
        uint32_t P[2][8][2];
#pragma unroll
        for (int mi = 0; mi < 2; mi++)
#pragma unroll
            for (int nt = 0; nt < 8; nt++) {
                float t0 = fmaf(S[mi][nt][0], LOG2E8, bias[nt].x);
                float t1 = fmaf(S[mi][nt][1], LOG2E8, bias[nt].y);
                float t2 = fmaf(S[mi][nt][2], LOG2E8, bias[nt].x);
                float t3 = fmaf(S[mi][nt][3], LOG2E8, bias[nt].y);
                uint32_t p01 = ex2_f16x2(t0, t1);
                uint32_t p23 = ex2_f16x2(t2, t3);
                P[mi][nt][0] = p01;
                P[mi][nt][1] = p23;
                // lrow[mi*2] += p0+p1 ; lrow[mi*2+1] += p2+p3 (per-half pairing)
                __half2 ha = *(__half2*)&p01;
                __half2 hb = *(__half2*)&p23;
                lrow[mi * 2]     += __half2float(__hadd(ha.x, ha.y));
                lrow[mi * 2 + 1] += __half2float(__hadd(hb.x, hb.y));
            }

        // ---- O += P V
#pragma unroll
        for (int step = 0; step < 4; step++) {
            uint32_t ah[2][4];
#pragma unroll
            for (int mi = 0; mi < 2; mi++)
#pragma unroll
                for (int t2 = 0; t2 < 2; t2++) {
                    ah[mi][t2 * 2]     = P[mi][2 * step + t2][0];
                    ah[mi][t2 * 2 + 1] = P[mi][2 * step + t2][1];
                }
            uint32_t vb[4][4];
#pragma unroll
            for (int g = 0; g < 4; g++) {
                int vrow = step * 16 + krV;
                int seg = g * 2 + nsegV;
                ldsm4t(vb[g], stg + 8192u + (uint32_t)vrow * 128
                       + (uint32_t)(((seg ^ (vrow & 7)) << 4)));
            }
#pragma unroll
            for (int mi = 0; mi < 2; mi++)
#pragma unroll
                for (int nt = 0; nt < 8; nt++)
                    mma16816h(O[mi][nt], ah[mi], vb[nt >> 1][nt & 1],
                              vb[nt >> 1][(nt & 1) + 2]);
        }

        __syncthreads();
    }

    // ---- normalize + store fp16
#pragma unroll
    for (int s = 0; s < 4; s++) {
        lrow[s] += __shfl_xor_sync(0xffffffffu, lrow[s], 1);
        lrow[s] += __shfl_xor_sync(0xffffffffu, lrow[s], 2);
        lrow[s] = 1.0f / lrow[s];
    }
    int rr = lane >> 2, cc = 2 * (lane & 3);
#pragma unroll
    for (int mi = 0; mi < 2; mi++)
#pragma unroll
        for (int nt = 0; nt < 8; nt++) {
            int tok0 = b * T_LEN + wi * 256 + w0 + mi * 16 + rr;
            int col = h * 64 + nt * 8 + cc;
            float i0 = lrow[mi * 2], i1 = lrow[mi * 2 + 1];
            __half2 v0 = __floats2half2_rn(O[mi][nt][0] * i0, O[mi][nt][1] * i0);
            __half2 v1 = __floats2half2_rn(O[mi][nt][2] * i1, O[mi][nt][3] * i1);
            *(__half2*)(AO + (size_t)tok0 * CDIM + col) = v0;
            *(__half2*)(AO + (size_t)(tok0 + 8) * CDIM + col) = v1;
        }
}

// ---------------- launch --------------------------------------------------------
extern "C" void kernel_launch(void* const* d_in, const int* in_sizes, int n_in,
                              void* d_out, int out_size) {
    const float* x    = (const float*)d_in[0];
    const void*  pm   = d_in[1];
    const float* cosT = (const float*)d_in[2];
    const float* sinT = (const float*)d_in[3];
    const float* Wq   = (const float*)d_in[4];
    const float* bq   = (const float*)d_in[5];
    const float* Wk   = (const float*)d_in[6];
    const float* bk   = (const float*)d_in[7];
    const float* Wv   = (const float*)d_in[8];
    const float* bv   = (const float*)d_in[9];
    const float* Wo   = (const float*)d_in[10];
    const float* bo   = (const float*)d_in[11];
    float* out = (float*)d_out;

    __half *XH, *AOH, *WH, *QH, *KH, *VH;
    cudaGetSymbolAddress((void**)&XH, g_XH);
    cudaGetSymbolAddress((void**)&AOH, g_AOH);
    cudaGetSymbolAddress((void**)&WH, g_WH);
    cudaGetSymbolAddress((void**)&QH, g_QH);
    cudaGetSymbolAddress((void**)&KH, g_KH);
    cudaGetSymbolAddress((void**)&VH, g_VH);

    cudaFuncSetAttribute(gemm_qkv, cudaFuncAttributeMaxDynamicSharedMemorySize, SMEM_GEMM);
    cudaFuncSetAttribute(gemm_f16, cudaFuncAttributeMaxDynamicSharedMemorySize, SMEM_GEMM);
    cudaFuncSetAttribute(attn_mma, cudaFuncAttributeMaxDynamicSharedMemorySize, SMEM_ATTN);

    // order chosen so ncu (-s 5 -c 1) profiles attn_mma (launch #6)
    to_half<<<NTOK * CDIM / 1024, 256>>>(x, XH);
    to_half_w<<<dim3(CDIM * CDIM / 1024, 4), 256>>>(Wq, Wk, Wv, Wo, WH);
    detect_mask<<<1, 256>>>((const unsigned int*)pm);
    build_attend<<<NWIN_TOT, 512>>>(pm);

    dim3 gq(CDIM / 128, NTOK / 128, 3);
    gemm_qkv<<<gq, 256, SMEM_GEMM>>>(XH, WH, bq, bk, bv, cosT, sinT, QH, KH, VH);

    attn_mma<<<dim3(NHEAD, NWIN_TOT), 256, SMEM_ATTN>>>(QH, KH, VH, AOH);

    dim3 gg(CDIM / 128, NTOK / 128);
    gemm_f16<<<gg, 256, SMEM_GEMM>>>(AOH, WH + 3 * (size_t)CDIM * CDIM, bo, out);
}

// round 16
// speedup vs baseline: 1.0038x; 1.0038x over previous
#include <cuda_runtime.h>
#include <cuda_bf16.h>
#include <cuda_fp16.h>
#include <cstdint>

#define T_LEN 8192
#define BATCH 2
#define CDIM 1024
#define NHEAD 16
#define HDIM 64
#define WINSZ 256
#define NWIN_TOT 64
#define NTOK (BATCH * T_LEN)     // 16384

// ---------------- scratch ----------------------------------------------------
__device__ __half g_XH[(size_t)NTOK * CDIM];        // x, fp16
__device__ __half g_AOH[(size_t)NTOK * CDIM];       // attn out, fp16
__device__ __half g_WH[4][(size_t)CDIM * CDIM];     // weights, fp16
__device__ __half g_QH[(size_t)NTOK * NHEAD * 64];  // rope'd Q fp16 [tok*16+h][64]
__device__ __half g_KH[(size_t)NTOK * NHEAD * 64];
__device__ __half g_VH[(size_t)NTOK * NHEAD * 64];
__device__ unsigned char g_attend[NWIN_TOT * 512];

// ---------------- helpers ------------------------------------------------------
__device__ __forceinline__ uint32_t smem_u32(const void* p) {
    uint32_t a;
    asm("{ .reg .u64 t; cvta.to.shared.u64 t, %1; cvt.u32.u64 %0, t; }" : "=r"(a) : "l"(p));
    return a;
}
__device__ __forceinline__ void cp16(uint32_t dst, const void* src) {
    asm volatile("cp.async.cg.shared.global [%0], [%1], 16;" :: "r"(dst), "l"(src));
}
__device__ __forceinline__ void cp16z(uint32_t dst, const void* src, uint32_t sz) {
    asm volatile("cp.async.cg.shared.global [%0], [%1], 16, %2;" :: "r"(dst), "l"(src), "r"(sz));
}
__device__ __forceinline__ void cp_commit() { asm volatile("cp.async.commit_group;"); }
template <int N> __device__ __forceinline__ void cp_wait() {
    asm volatile("cp.async.wait_group %0;" :: "n"(N));
}
__device__ __forceinline__ void ldsm4(uint32_t (&r)[4], uint32_t addr) {
    asm volatile("ldmatrix.sync.aligned.m8n8.x4.shared.b16 {%0,%1,%2,%3}, [%4];"
                 : "=r"(r[0]), "=r"(r[1]), "=r"(r[2]), "=r"(r[3]) : "r"(addr));
}
__device__ __forceinline__ void ldsm4t(uint32_t (&r)[4], uint32_t addr) {
    asm volatile("ldmatrix.sync.aligned.m8n8.x4.trans.shared.b16 {%0,%1,%2,%3}, [%4];"
                 : "=r"(r[0]), "=r"(r[1]), "=r"(r[2]), "=r"(r[3]) : "r"(addr));
}
__device__ __forceinline__ void mma16816h(float (&c)[4], const uint32_t (&a)[4],
                                          uint32_t b0, uint32_t b1) {
    asm volatile(
        "mma.sync.aligned.m16n8k16.row.col.f32.f16.f16.f32 "
        "{%0,%1,%2,%3}, {%4,%5,%6,%7}, {%8,%9}, {%0,%1,%2,%3};"
        : "+f"(c[0]), "+f"(c[1]), "+f"(c[2]), "+f"(c[3])
        : "r"(a[0]), "r"(a[1]), "r"(a[2]), "r"(a[3]), "r"(b0), "r"(b1));
}
__device__ __forceinline__ uint32_t ex2_f16x2(float t0, float t1) {
    __half2 h = __floats2half2_rn(t0, t1);
    uint32_t r;
    asm("ex2.approx.f16x2 %0, %1;" : "=r"(r) : "r"(*(uint32_t*)&h));
    return r;
}

// ---------------- fused fp32 -> fp16 conversion (x + 4 weights) ----------------
// grid: 16384 blocks for x (float4 per thread), then 4 x 1024 blocks for weights.
__global__ void convert_all(const float* __restrict__ x,
                            const float* __restrict__ w0, const float* __restrict__ w1,
                            const float* __restrict__ w2, const float* __restrict__ w3,
                            __half* __restrict__ XH, __half* __restrict__ WH) {
    int bx = blockIdx.x;
    const float* in;
    __half* out;
    int i;
    if (bx < 16384) {
        in = x; out = XH;
        i = bx * 256 + threadIdx.x;
    } else {
        int z = (bx - 16384) >> 10;
        in = (z == 0) ? w0 : ((z == 1) ? w1 : ((z == 2) ? w2 : w3));
        out = WH + (size_t)z * CDIM * CDIM;
        i = ((bx - 16384) & 1023) * 256 + threadIdx.x;
    }
    float4 v = ((const float4*)in)[i];
    __half2 h01 = __floats2half2_rn(v.x, v.y);
    __half2 h23 = __floats2half2_rn(v.z, v.w);
    ((__half2*)out)[2 * i] = h01;
    ((__half2*)out)[2 * i + 1] = h23;
}

// ---------------- fp16 GEMM, 128x128 CTA tile, 256 threads (R10-proven) --------
#define GK 1024
#define CH 16
#define NST 3
#define STAGE_B 32768             // A 16KB + B 16KB
#define SMEM_GEMM (NST * STAGE_B)

__device__ __forceinline__ void load_chunk(uint32_t stage, const __half* Arow,
                                           const __half* Brow, int kbase, int tid) {
#pragma unroll
    for (int i = 0; i < 4; i++) {
        int f = tid + i * 256;
        int rr = f >> 3, seg = f & 7;
        uint32_t off = rr * 128 + seg * 16;
        uint32_t sw = off ^ ((off >> 3) & 0x70);
        cp16(stage + sw, Arow + (size_t)rr * GK + kbase + seg * 8);
        cp16(stage + 16384 + sw, Brow + (size_t)rr * GK + kbase + seg * 8);
    }
}

__device__ __forceinline__ void gemm_mainloop(char* dsm, const __half* Arow,
        const __half* Brow, int tid, int lane, int m0, int n0,
        float (&acc)[2][8][4]) {
    uint32_t sbase = smem_u32(dsm);

    int rA = m0 + (lane & 7) + ((lane >> 3) & 1) * 8;
    int ksegA = lane >> 4;
    int swA = rA & 7;
    int rB = n0 + (lane & 7) + ((lane >> 4) << 3);
    int ksegB = (lane >> 3) & 1;
    int swB = rB & 7;

    uint32_t aRowOff[2], bRowOff[4];
#pragma unroll
    for (int mi = 0; mi < 2; mi++) aRowOff[mi] = (uint32_t)(rA + mi * 16) * 128;
#pragma unroll
    for (int g = 0; g < 4; g++) bRowOff[g] = 16384u + (uint32_t)(rB + g * 16) * 128;

#pragma unroll
    for (int mi = 0; mi < 2; mi++)
#pragma unroll
        for (int nt = 0; nt < 8; nt++)
#pragma unroll
            for (int j = 0; j < 4; j++) acc[mi][nt][j] = 0.0f;

    load_chunk(sbase, Arow, Brow, 0, tid);
    cp_commit();
    load_chunk(sbase + STAGE_B, Arow, Brow, 64, tid);
    cp_commit();

    for (int c = 0; c < CH; c++) {
        if (c + 2 < CH) load_chunk(sbase + ((c + 2) % NST) * STAGE_B, Arow, Brow,
                                   (c + 2) * 64, tid);
        cp_commit();
        cp_wait<2>();
        __syncthreads();

        uint32_t stg = sbase + (c % NST) * STAGE_B;
#pragma unroll
        for (int step = 0; step < 4; step++) {
            uint32_t a[2][4];
#pragma unroll
            for (int mi = 0; mi < 2; mi++)
                ldsm4(a[mi], stg + aRowOff[mi] + ((uint32_t)((step * 2 + ksegA) ^ swA) << 4));
            uint32_t b[4][4];
#pragma unroll
            for (int g = 0; g < 4; g++)
                ldsm4(b[g], stg + bRowOff[g] + ((uint32_t)((step * 2 + ksegB) ^ swB) << 4));
#pragma unroll
            for (int mi = 0; mi < 2; mi++)
#pragma unroll
                for (int nt = 0; nt < 8; nt++)
                    mma16816h(acc[mi][nt], a[mi], b[nt >> 1][(nt & 1) * 2],
                              b[nt >> 1][(nt & 1) * 2 + 1]);
        }
        __syncthreads();
    }
}

// ---------------- fused QKV GEMM: bias + (rope) + fp16 store -------------------
__global__ void __launch_bounds__(256) gemm_qkv(const __half* __restrict__ A,
        const __half* __restrict__ WHbase,
        const float* __restrict__ bq, const float* __restrict__ bk,
        const float* __restrict__ bv,
        const float* __restrict__ cosT, const float* __restrict__ sinT,
        __half* __restrict__ QH, __half* __restrict__ KH, __half* __restrict__ VH) {
    extern __shared__ char dsm[];
    int which = blockIdx.z;
    const __half* W = WHbase + (size_t)which * CDIM * CDIM;
    const float* bias = (which == 0) ? bq : ((which == 1) ? bk : bv);
    __half* outH = (which == 0) ? QH : ((which == 1) ? KH : VH);

    int tid = threadIdx.x;
    int wid = tid >> 5, lane = tid & 31;
    int row0 = blockIdx.y * 128;
    int col0 = blockIdx.x * 128;
    int m0 = (wid & 3) * 32;
    int n0 = (wid >> 2) * 64;

    float acc[2][8][4];
    gemm_mainloop(dsm, A + (size_t)row0 * GK, W + (size_t)col0 * GK,
                  tid, lane, m0, n0, acc);

    int g = lane >> 2;
    int cl = (lane & 3) * 2;
    int hh = (col0 + n0) >> 6;

#pragma unroll
    for (int mi = 0; mi < 2; mi++)
#pragma unroll
        for (int nt = 0; nt < 8; nt++) {
            int gcol = col0 + n0 + nt * 8 + cl;
            float b0 = bias[gcol], b1 = bias[gcol + 1];
            acc[mi][nt][0] += b0; acc[mi][nt][1] += b1;
            acc[mi][nt][2] += b0; acc[mi][nt][3] += b1;
        }

    if (which < 2) {   // rope on Q, K
#pragma unroll
        for (int mi = 0; mi < 2; mi++) {
            int r0 = row0 + m0 + mi * 16 + g;
            int pos0 = r0 & (T_LEN - 1);
            const float* c0 = cosT + (size_t)pos0 * HDIM;
            const float* s0 = sinT + (size_t)pos0 * HDIM;
            const float* c1 = c0 + 8 * HDIM;
            const float* s1 = s0 + 8 * HDIM;
#pragma unroll
            for (int nt = 0; nt < 4; nt++) {
                int d = nt * 8 + cl;
                float2 cA0 = *(const float2*)(c0 + d), sA0 = *(const float2*)(s0 + d);
                float2 cB0 = *(const float2*)(c0 + d + 32), sB0 = *(const float2*)(s0 + d + 32);
                float2 cA1 = *(const float2*)(c1 + d), sA1 = *(const float2*)(s1 + d);
                float2 cB1 = *(const float2*)(c1 + d + 32), sB1 = *(const float2*)(s1 + d + 32);
                float a, b;
                a = acc[mi][nt][0]; b = acc[mi][nt + 4][0];
                acc[mi][nt][0]     = a * cA0.x - b * sA0.x;
                acc[mi][nt + 4][0] = b * cB0.x + a * sB0.x;
                a = acc[mi][nt][1]; b = acc[mi][nt + 4][1];
                acc[mi][nt][1]     = a * cA0.y - b * sA0.y;
                acc[mi][nt + 4][1] = b * cB0.y + a * sB0.y;
                a = acc[mi][nt][2]; b = acc[mi][nt + 4][2];
                acc[mi][nt][2]     = a * cA1.x - b * sA1.x;
                acc[mi][nt + 4][2] = b * cB1.x + a * sB1.x;
                a = acc[mi][nt][3]; b = acc[mi][nt + 4][3];
                acc[mi][nt][3]     = a * cA1.y - b * sA1.y;
                acc[mi][nt + 4][3] = b * cB1.y + a * sB1.y;
            }
        }
    }

#pragma unroll
    for (int mi = 0; mi < 2; mi++) {
        int r0 = row0 + m0 + mi * 16 + g;
        __half* o0 = outH + ((size_t)r0 * NHEAD + hh) * 64;
        __half* o1 = outH + ((size_t)(r0 + 8) * NHEAD + hh) * 64;
#pragma unroll
        for (int nt = 0; nt < 8; nt++) {
            int d = nt * 8 + cl;
            __half2 v0 = __floats2half2_rn(acc[mi][nt][0], acc[mi][nt][1]);
            __half2 v1 = __floats2half2_rn(acc[mi][nt][2], acc[mi][nt][3]);
            *(__half2*)(o0 + d) = v0;
            *(__half2*)(o1 + d) = v1;
        }
    }
}

// ---------------- O-projection GEMM: fp32 out + bias ---------------------------
__global__ void __launch_bounds__(256) gemm_f16(const __half* __restrict__ A,
        const __half* __restrict__ Bw, const float* __restrict__ bias,
        float* __restrict__ C) {
    extern __shared__ char dsm[];
    int tid = threadIdx.x;
    int wid = tid >> 5, lane = tid & 31;
    int row0 = blockIdx.y * 128;
    int col0 = blockIdx.x * 128;
    int m0 = (wid & 3) * 32;
    int n0 = (wid >> 2) * 64;

    float acc[2][8][4];
    gemm_mainloop(dsm, A + (size_t)row0 * GK, Bw + (size_t)col0 * GK,
                  tid, lane, m0, n0, acc);

    int g = lane >> 2;
    int cl = (lane & 3) * 2;
#pragma unroll
    for (int mi = 0; mi < 2; mi++) {
#pragma unroll
        for (int nt = 0; nt < 8; nt++) {
            int gcol = col0 + n0 + nt * 8 + cl;
            float b0 = bias[gcol], b1 = bias[gcol + 1];
            int r0 = row0 + m0 + mi * 16 + g;
            float2 v0 = make_float2(acc[mi][nt][0] + b0, acc[mi][nt][1] + b1);
            float2 v1 = make_float2(acc[mi][nt][2] + b0, acc[mi][nt][3] + b1);
            *(float2*)(C + (size_t)r0 * CDIM + gcol) = v0;
            *(float2*)(C + (size_t)(r0 + 8) * CDIM + gcol) = v1;
        }
    }
}

// ---------------- fused mask: dtype detection + attend mask -------------------
__global__ void fused_mask(const void* __restrict__ pm) {
    __shared__ int okf, oki;
    int j = threadIdx.x;        // 0..511
    int w = blockIdx.x;         // 0..63
    if (j == 0) { okf = 1; oki = 1; }
    __syncthreads();
    const unsigned int* m32 = (const unsigned int*)pm;
    for (int i = j; i < 4096; i += 512) {
        unsigned int v = m32[i];
        if (v != 0u && v != 0x3f800000u) okf = 0;
        if (v > 1u) oki = 0;
    }
    __syncthreads();
    int mm = okf ? 2 : (oki ? 1 : 0);

    int b = w >> 5;
    int wi = w & 31;
    int p = wi * WINSZ - 128 + j;
    int attend = 1;
    if ((unsigned)p < (unsigned)T_LEN) {
        size_t im = (size_t)b * T_LEN + p;
        int v;
        if (mm == 0)      v = ((const unsigned char*)pm)[im] != 0;
        else if (mm == 1) v = ((const int*)pm)[im] != 0;
        else              v = ((const float*)pm)[im] != 0.0f;
        attend = !v;
    }
    __shared__ int allb;
    if (j == 0) allb = 1;
    __syncthreads();
    if (!attend) allb = 0;
    __syncthreads();
    if (j == 0 && allb) attend = 0;
    g_attend[w * 512 + j] = (unsigned char)attend;
}

// ---------------- tensor-core windowed attention (R14 champion config) --------
#define ATT_STG 32768
#define ATT_BIAS 65536
#define SMEM_ATTN (1024 + 65536 + 256)
#define LOG2E8 0.18033688011112042f    // 0.125 * log2(e)

__device__ __forceinline__ void load_kv_chunk(uint32_t stg, const __half* KH,
        const __half* VH, int b, int h, int p0, int tid) {
#pragma unroll
    for (int i = 0; i < 2; i++) {
        int f = tid + i * 256;
        int r = f >> 3, seg = f & 7;
        int p = p0 + r;
        uint32_t ok = ((unsigned)p < (unsigned)T_LEN) ? 16u : 0u;
        int pc = (p < 0) ? 0 : ((p >= T_LEN) ? (T_LEN - 1) : p);
        const __half* kk = KH + (((size_t)(b * T_LEN + pc) * NHEAD + h) << 6) + seg * 8;
        const __half* vv = VH + (((size_t)(b * T_LEN + pc) * NHEAD + h) << 6) + seg * 8;
        uint32_t sw = (uint32_t)r * 128 + (uint32_t)(((seg ^ (r & 7)) << 4));
        cp16z(stg + sw, kk, ok);
        cp16z(stg + 8192 + sw, vv, ok);
    }
}

__global__ void __launch_bounds__(256) attn_mma(
        const __half* __restrict__ QH, const __half* __restrict__ KH,
        const __half* __restrict__ VH, __half* __restrict__ AO) {
    extern __shared__ char sm[];
    char* smA = (char*)(((uintptr_t)sm + 1023) & ~(uintptr_t)1023);
    uint32_t sb = smem_u32(smA);
    float* biasP = (float*)(smA + ATT_BIAS);

    int h = blockIdx.x, w = blockIdx.y;
    int b = w >> 5, wi = w & 31;
    int tid = threadIdx.x, wid = tid >> 5, lane = tid & 31;
    int w0 = wid * 32;

    int rA = (lane & 7) + ((lane >> 3) & 1) * 8;
    int ksegA = lane >> 4;
    int rB = (lane & 7) + ((lane >> 4) << 3);
    int ksegB = (lane >> 3) & 1;
    int krV = (lane & 7) + ((lane >> 4) << 3);
    int nsegV = (lane >> 3) & 1;

#pragma unroll
    for (int i = 0; i < 8; i++) {
        int f = tid + i * 256;
        int r = f >> 3, seg = f & 7;
        const __half* q = QH + (((size_t)(b * T_LEN + wi * 256 + r) * NHEAD + h) << 6)
                          + seg * 8;
        uint32_t sw = (uint32_t)r * 128 + (uint32_t)(((seg ^ (r & 7)) << 4));
        cp16(sb + sw, q);
    }
    load_kv_chunk(sb + ATT_STG, KH, VH, b, h, wi * 256 - 128, tid);
    cp_commit();
    load_kv_chunk(sb + ATT_STG + 16384, KH, VH, b, h, wi * 256 - 64, tid);
    cp_commit();

    float O[2][8][4];
#pragma unroll
    for (int mi = 0; mi < 2; mi++)
#pragma unroll
        for (int nt = 0; nt < 8; nt++)
#pragma unroll
            for (int j = 0; j < 4; j++) O[mi][nt][j] = 0.0f;
    float lrow[4] = {0.f, 0.f, 0.f, 0.f};

    for (int c = 0; c < 8; c++) {
        if (c < 6) { cp_wait<1>(); } else { cp_wait<0>(); }
        if (tid < 64)
            biasP[tid] = g_attend[w * 512 + c * 64 + tid] ? 0.0f : -30000.0f;
        __syncthreads();

        uint32_t stg = sb + ATT_STG + (uint32_t)(c & 1) * 16384u;

        // ---- S = Q K^T
        float S[2][8][4];
#pragma unroll
        for (int mi = 0; mi < 2; mi++)
#pragma unroll
            for (int nt = 0; nt < 8; nt++)
#pragma unroll
                for (int j = 0; j < 4; j++) S[mi][nt][j] = 0.0f;

#pragma unroll
        for (int step = 0; step < 4; step++) {
            uint32_t kb[4][4];
#pragma unroll
            for (int g = 0; g < 4; g++) {
                int row = g * 16 + rB;
                ldsm4(kb[g], stg + (uint32_t)row * 128
                      + (uint32_t)(((step * 2 + ksegB) ^ (row & 7)) << 4));
            }
#pragma unroll
            for (int mi = 0; mi < 2; mi++) {
                int rowQ = w0 + mi * 16 + rA;
                uint32_t qf[4];
                ldsm4(qf, sb + (uint32_t)rowQ * 128
                      + (uint32_t)(((step * 2 + ksegA) ^ (rowQ & 7)) << 4));
#pragma unroll
                for (int nt = 0; nt < 8; nt++)
                    mma16816h(S[mi][nt], qf, kb[nt >> 1][(nt & 1) * 2],
                              kb[nt >> 1][(nt & 1) * 2 + 1]);
            }
        }

        // ---- P = ex2(S*0.125*log2e + bias) in fp16x2
        float2 bias[8];
#pragma unroll
        for (int nt = 0; nt < 8; nt++)
            bias[nt] = *(float2*)&biasP[nt * 8 + 2 * (lane & 3)];
        uint32_t P[2][8][2];
#pragma unroll
        for (int mi = 0; mi < 2; mi++)
#pragma unroll
            for (int nt = 0; nt < 8; nt++) {
                float t0 = fmaf(S[mi][nt][0], LOG2E8, bias[nt].x);
                float t1 = fmaf(S[mi][nt][1], LOG2E8, bias[nt].y);
                float t2 = fmaf(S[mi][nt][2], LOG2E8, bias[nt].x);
                float t3 = fmaf(S[mi][nt][3], LOG2E8, bias[nt].y);
                uint32_t p01 = ex2_f16x2(t0, t1);
                uint32_t p23 = ex2_f16x2(t2, t3);
                P[mi][nt][0] = p01;
                P[mi][nt][1] = p23;
                float2 fa = __half22float2(*(__half2*)&p01);
                float2 fb = __half22float2(*(__half2*)&p23);
                lrow[mi * 2]     += fa.x + fa.y;
                lrow[mi * 2 + 1] += fb.x + fb.y;
            }

        // ---- O += P V
#pragma unroll
        for (int step = 0; step < 4; step++) {
            uint32_t ah[2][4];
#pragma unroll
            for (int mi = 0; mi < 2; mi++)
#pragma unroll
                for (int t2 = 0; t2 < 2; t2++) {
                    ah[mi][t2 * 2]     = P[mi][2 * step + t2][0];
                    ah[mi][t2 * 2 + 1] = P[mi][2 * step + t2][1];
                }
            uint32_t vb[4][4];
#pragma unroll
            for (int g = 0; g < 4; g++) {
                int vrow = step * 16 + krV;
                int seg = g * 2 + nsegV;
                ldsm4t(vb[g], stg + 8192u + (uint32_t)vrow * 128
                       + (uint32_t)(((seg ^ (vrow & 7)) << 4)));
            }
#pragma unroll
            for (int mi = 0; mi < 2; mi++)
#pragma unroll
                for (int nt = 0; nt < 8; nt++)
                    mma16816h(O[mi][nt], ah[mi], vb[nt >> 1][nt & 1],
                              vb[nt >> 1][(nt & 1) + 2]);
        }

        __syncthreads();
        if (c + 2 < 8) {
            load_kv_chunk(sb + ATT_STG + (uint32_t)(c & 1) * 16384u, KH, VH, b, h,
                          wi * 256 - 128 + (c + 2) * 64, tid);
            cp_commit();
        }
    }

    // ---- normalize + store fp16
#pragma unroll
    for (int s = 0; s < 4; s++) {
        lrow[s] += __shfl_xor_sync(0xffffffffu, lrow[s], 1);
        lrow[s] += __shfl_xor_sync(0xffffffffu, lrow[s], 2);
        lrow[s] = 1.0f / lrow[s];
    }
    int rr = lane >> 2, cc = 2 * (lane & 3);
#pragma unroll
    for (int mi = 0; mi < 2; mi++)
#pragma unroll
        for (int nt = 0; nt < 8; nt++) {
            int tok0 = b * T_LEN + wi * 256 + w0 + mi * 16 + rr;
            int col = h * 64 + nt * 8 + cc;
            float i0 = lrow[mi * 2], i1 = lrow[mi * 2 + 1];
            __half2 v0 = __floats2half2_rn(O[mi][nt][0] * i0, O[mi][nt][1] * i0);
            __half2 v1 = __floats2half2_rn(O[mi][nt][2] * i1, O[mi][nt][3] * i1);
            *(__half2*)(AO + (size_t)tok0 * CDIM + col) = v0;
            *(__half2*)(AO + (size_t)(tok0 + 8) * CDIM + col) = v1;
        }
}

// ---------------- launch --------------------------------------------------------
extern "C" void kernel_launch(void* const* d_in, const int* in_sizes, int n_in,
                              void* d_out, int out_size) {
    const float* x    = (const float*)d_in[0];
    const void*  pm   = d_in[1];
    const float* cosT = (const float*)d_in[2];
    const float* sinT = (const float*)d_in[3];
    const float* Wq   = (const float*)d_in[4];
    const float* bq   = (const float*)d_in[5];
    const float* Wk   = (const float*)d_in[6];
    const float* bk   = (const float*)d_in[7];
    const float* Wv   = (const float*)d_in[8];
    const float* bv   = (const float*)d_in[9];
    const float* Wo   = (const float*)d_in[10];
    const float* bo   = (const float*)d_in[11];
    float* out = (float*)d_out;

    __half *XH, *AOH, *WH, *QH, *KH, *VH;
    cudaGetSymbolAddress((void**)&XH, g_XH);
    cudaGetSymbolAddress((void**)&AOH, g_AOH);
    cudaGetSymbolAddress((void**)&WH, g_WH);
    cudaGetSymbolAddress((void**)&QH, g_QH);
    cudaGetSymbolAddress((void**)&KH, g_KH);
    cudaGetSymbolAddress((void**)&VH, g_VH);

    cudaFuncSetAttribute(gemm_qkv, cudaFuncAttributeMaxDynamicSharedMemorySize, SMEM_GEMM);
    cudaFuncSetAttribute(gemm_f16, cudaFuncAttributeMaxDynamicSharedMemorySize, SMEM_GEMM);
    cudaFuncSetAttribute(attn_mma, cudaFuncAttributeMaxDynamicSharedMemorySize, SMEM_ATTN);

    convert_all<<<16384 + 4096, 256>>>(x, Wq, Wk, Wv, Wo, XH, WH);
    fused_mask<<<NWIN_TOT, 512>>>(pm);

    dim3 gq(CDIM / 128, NTOK / 128, 3);
    gemm_qkv<<<gq, 256, SMEM_GEMM>>>(XH, WH, bq, bk, bv, cosT, sinT, QH, KH, VH);

    attn_mma<<<dim3(NHEAD, NWIN_TOT), 256, SMEM_ATTN>>>(QH, KH, VH, AOH);

    dim3 gg(CDIM / 128, NTOK / 128);
    gemm_f16<<<gg, 256, SMEM_GEMM>>>(AOH, WH + 3 * (size_t)CDIM * CDIM, bo, out);
}

// round 17
// speedup vs baseline: 1.0327x; 1.0288x over previous
#include <cuda_runtime.h>
#include <cuda_bf16.h>
#include <cuda_fp16.h>
#include <cstdint>

#define T_LEN 8192
#define BATCH 2
#define CDIM 1024
#define NHEAD 16
#define HDIM 64
#define WINSZ 256
#define NWIN_TOT 64
#define NTOK (BATCH * T_LEN)     // 16384

// ---------------- scratch ----------------------------------------------------
__device__ __half g_XH[(size_t)NTOK * CDIM];        // x, fp16
__device__ __half g_AOH[(size_t)NTOK * CDIM];       // attn out, fp16
__device__ __half g_WH[4][(size_t)CDIM * CDIM];     // weights, fp16
__device__ __half g_QH[(size_t)NTOK * NHEAD * 64];  // rope'd Q fp16 [tok*16+h][64]
__device__ __half g_KH[(size_t)NTOK * NHEAD * 64];
__device__ __half g_VH[(size_t)NTOK * NHEAD * 64];
__device__ unsigned char g_attend[NWIN_TOT * 512];

// ---------------- helpers ------------------------------------------------------
__device__ __forceinline__ uint32_t smem_u32(const void* p) {
    uint32_t a;
    asm("{ .reg .u64 t; cvta.to.shared.u64 t, %1; cvt.u32.u64 %0, t; }" : "=r"(a) : "l"(p));
    return a;
}
__device__ __forceinline__ void cp16(uint32_t dst, const void* src) {
    asm volatile("cp.async.cg.shared.global [%0], [%1], 16;" :: "r"(dst), "l"(src));
}
__device__ __forceinline__ void cp16z(uint32_t dst, const void* src, uint32_t sz) {
    asm volatile("cp.async.cg.shared.global [%0], [%1], 16, %2;" :: "r"(dst), "l"(src), "r"(sz));
}
__device__ __forceinline__ void cp_commit() { asm volatile("cp.async.commit_group;"); }
template <int N> __device__ __forceinline__ void cp_wait() {
    asm volatile("cp.async.wait_group %0;" :: "n"(N));
}
__device__ __forceinline__ void ldsm4(uint32_t (&r)[4], uint32_t addr) {
    asm volatile("ldmatrix.sync.aligned.m8n8.x4.shared.b16 {%0,%1,%2,%3}, [%4];"
                 : "=r"(r[0]), "=r"(r[1]), "=r"(r[2]), "=r"(r[3]) : "r"(addr));
}
__device__ __forceinline__ void ldsm4t(uint32_t (&r)[4], uint32_t addr) {
    asm volatile("ldmatrix.sync.aligned.m8n8.x4.trans.shared.b16 {%0,%1,%2,%3}, [%4];"
                 : "=r"(r[0]), "=r"(r[1]), "=r"(r[2]), "=r"(r[3]) : "r"(addr));
}
__device__ __forceinline__ void mma16816h(float (&c)[4], const uint32_t (&a)[4],
                                          uint32_t b0, uint32_t b1) {
    asm volatile(
        "mma.sync.aligned.m16n8k16.row.col.f32.f16.f16.f32 "
        "{%0,%1,%2,%3}, {%4,%5,%6,%7}, {%8,%9}, {%0,%1,%2,%3};"
        : "+f"(c[0]), "+f"(c[1]), "+f"(c[2]), "+f"(c[3])
        : "r"(a[0]), "r"(a[1]), "r"(a[2]), "r"(a[3]), "r"(b0), "r"(b1));
}
__device__ __forceinline__ uint32_t ex2_f16x2(float t0, float t1) {
    __half2 h = __floats2half2_rn(t0, t1);
    uint32_t r;
    asm("ex2.approx.f16x2 %0, %1;" : "=r"(r) : "r"(*(uint32_t*)&h));
    return r;
}

// ---------------- fused fp32 -> fp16 conversion (x + 4 weights) ----------------
__global__ void convert_all(const float* __restrict__ x,
                            const float* __restrict__ w0, const float* __restrict__ w1,
                            const float* __restrict__ w2, const float* __restrict__ w3,
                            __half* __restrict__ XH, __half* __restrict__ WH) {
    int bx = blockIdx.x;
    const float* in;
    __half* out;
    int i;
    if (bx < 16384) {
        in = x; out = XH;
        i = bx * 256 + threadIdx.x;
    } else {
        int z = (bx - 16384) >> 10;
        in = (z == 0) ? w0 : ((z == 1) ? w1 : ((z == 2) ? w2 : w3));
        out = WH + (size_t)z * CDIM * CDIM;
        i = ((bx - 16384) & 1023) * 256 + threadIdx.x;
    }
    float4 v = ((const float4*)in)[i];
    __half2 h01 = __floats2half2_rn(v.x, v.y);
    __half2 h23 = __floats2half2_rn(v.z, v.w);
    ((__half2*)out)[2 * i] = h01;
    ((__half2*)out)[2 * i + 1] = h23;
}

// ---------------- fp16 GEMM, 128x128 CTA tile, 256 threads (R10-proven) --------
#define GK 1024
#define CH 16
#define NST 3
#define STAGE_B 32768             // A 16KB + B 16KB
#define SMEM_GEMM (NST * STAGE_B)

__device__ __forceinline__ void load_chunk(uint32_t stage, const __half* Arow,
                                           const __half* Brow, int kbase, int tid) {
#pragma unroll
    for (int i = 0; i < 4; i++) {
        int f = tid + i * 256;
        int rr = f >> 3, seg = f & 7;
        uint32_t off = rr * 128 + seg * 16;
        uint32_t sw = off ^ ((off >> 3) & 0x70);
        cp16(stage + sw, Arow + (size_t)rr * GK + kbase + seg * 8);
        cp16(stage + 16384 + sw, Brow + (size_t)rr * GK + kbase + seg * 8);
    }
}

__device__ __forceinline__ void gemm_mainloop(char* dsm, const __half* Arow,
        const __half* Brow, int tid, int lane, int m0, int n0,
        float (&acc)[2][8][4]) {
    uint32_t sbase = smem_u32(dsm);

    int rA = m0 + (lane & 7) + ((lane >> 3) & 1) * 8;
    int ksegA = lane >> 4;
    int swA = rA & 7;
    int rB = n0 + (lane & 7) + ((lane >> 4) << 3);
    int ksegB = (lane >> 3) & 1;
    int swB = rB & 7;

    uint32_t aRowOff[2], bRowOff[4];
#pragma unroll
    for (int mi = 0; mi < 2; mi++) aRowOff[mi] = (uint32_t)(rA + mi * 16) * 128;
#pragma unroll
    for (int g = 0; g < 4; g++) bRowOff[g] = 16384u + (uint32_t)(rB + g * 16) * 128;

#pragma unroll
    for (int mi = 0; mi < 2; mi++)
#pragma unroll
        for (int nt = 0; nt < 8; nt++)
#pragma unroll
            for (int j = 0; j < 4; j++) acc[mi][nt][j] = 0.0f;

    load_chunk(sbase, Arow, Brow, 0, tid);
    cp_commit();
    load_chunk(sbase + STAGE_B, Arow, Brow, 64, tid);
    cp_commit();

    for (int c = 0; c < CH; c++) {
        if (c + 2 < CH) load_chunk(sbase + ((c + 2) % NST) * STAGE_B, Arow, Brow,
                                   (c + 2) * 64, tid);
        cp_commit();
        cp_wait<2>();
        __syncthreads();

        uint32_t stg = sbase + (c % NST) * STAGE_B;
#pragma unroll
        for (int step = 0; step < 4; step++) {
            uint32_t a[2][4];
#pragma unroll
            for (int mi = 0; mi < 2; mi++)
                ldsm4(a[mi], stg + aRowOff[mi] + ((uint32_t)((step * 2 + ksegA) ^ swA) << 4));
            uint32_t b[4][4];
#pragma unroll
            for (int g = 0; g < 4; g++)
                ldsm4(b[g], stg + bRowOff[g] + ((uint32_t)((step * 2 + ksegB) ^ swB) << 4));
#pragma unroll
            for (int mi = 0; mi < 2; mi++)
#pragma unroll
                for (int nt = 0; nt < 8; nt++)
                    mma16816h(acc[mi][nt], a[mi], b[nt >> 1][(nt & 1) * 2],
                              b[nt >> 1][(nt & 1) * 2 + 1]);
        }
        __syncthreads();
    }
}

// ---------------- fused QKV GEMM: bias + (rope) + fp16 store -------------------
__global__ void __launch_bounds__(256) gemm_qkv(const __half* __restrict__ A,
        const __half* __restrict__ WHbase,
        const float* __restrict__ bq, const float* __restrict__ bk,
        const float* __restrict__ bv,
        const float* __restrict__ cosT, const float* __restrict__ sinT,
        __half* __restrict__ QH, __half* __restrict__ KH, __half* __restrict__ VH) {
    extern __shared__ char dsm[];
    int which = blockIdx.z;
    const __half* W = WHbase + (size_t)which * CDIM * CDIM;
    const float* bias = (which == 0) ? bq : ((which == 1) ? bk : bv);
    __half* outH = (which == 0) ? QH : ((which == 1) ? KH : VH);

    int tid = threadIdx.x;
    int wid = tid >> 5, lane = tid & 31;
    int row0 = blockIdx.y * 128;
    int col0 = blockIdx.x * 128;
    int m0 = (wid & 3) * 32;
    int n0 = (wid >> 2) * 64;

    float acc[2][8][4];
    gemm_mainloop(dsm, A + (size_t)row0 * GK, W + (size_t)col0 * GK,
                  tid, lane, m0, n0, acc);

    int g = lane >> 2;
    int cl = (lane & 3) * 2;
    int hh = (col0 + n0) >> 6;

#pragma unroll
    for (int mi = 0; mi < 2; mi++)
#pragma unroll
        for (int nt = 0; nt < 8; nt++) {
            int gcol = col0 + n0 + nt * 8 + cl;
            float b0 = bias[gcol], b1 = bias[gcol + 1];
            acc[mi][nt][0] += b0; acc[mi][nt][1] += b1;
            acc[mi][nt][2] += b0; acc[mi][nt][3] += b1;
        }

    if (which < 2) {   // rope on Q, K
#pragma unroll
        for (int mi = 0; mi < 2; mi++) {
            int r0 = row0 + m0 + mi * 16 + g;
            int pos0 = r0 & (T_LEN - 1);
            const float* c0 = cosT + (size_t)pos0 * HDIM;
            const float* s0 = sinT + (size_t)pos0 * HDIM;
            const float* c1 = c0 + 8 * HDIM;
            const float* s1 = s0 + 8 * HDIM;
#pragma unroll
            for (int nt = 0; nt < 4; nt++) {
                int d = nt * 8 + cl;
                float2 cA0 = *(const float2*)(c0 + d), sA0 = *(const float2*)(s0 + d);
                float2 cB0 = *(const float2*)(c0 + d + 32), sB0 = *(const float2*)(s0 + d + 32);
                float2 cA1 = *(const float2*)(c1 + d), sA1 = *(const float2*)(s1 + d);
                float2 cB1 = *(const float2*)(c1 + d + 32), sB1 = *(const float2*)(s1 + d + 32);
                float a, b;
                a = acc[mi][nt][0]; b = acc[mi][nt + 4][0];
                acc[mi][nt][0]     = a * cA0.x - b * sA0.x;
                acc[mi][nt + 4][0] = b * cB0.x + a * sB0.x;
                a = acc[mi][nt][1]; b = acc[mi][nt + 4][1];
                acc[mi][nt][1]     = a * cA0.y - b * sA0.y;
                acc[mi][nt + 4][1] = b * cB0.y + a * sB0.y;
                a = acc[mi][nt][2]; b = acc[mi][nt + 4][2];
                acc[mi][nt][2]     = a * cA1.x - b * sA1.x;
                acc[mi][nt + 4][2] = b * cB1.x + a * sB1.x;
                a = acc[mi][nt][3]; b = acc[mi][nt + 4][3];
                acc[mi][nt][3]     = a * cA1.y - b * sA1.y;
                acc[mi][nt + 4][3] = b * cB1.y + a * sB1.y;
            }
        }
    }

#pragma unroll
    for (int mi = 0; mi < 2; mi++) {
        int r0 = row0 + m0 + mi * 16 + g;
        __half* o0 = outH + ((size_t)r0 * NHEAD + hh) * 64;
        __half* o1 = outH + ((size_t)(r0 + 8) * NHEAD + hh) * 64;
#pragma unroll
        for (int nt = 0; nt < 8; nt++) {
            int d = nt * 8 + cl;
            __half2 v0 = __floats2half2_rn(acc[mi][nt][0], acc[mi][nt][1]);
            __half2 v1 = __floats2half2_rn(acc[mi][nt][2], acc[mi][nt][3]);
            *(__half2*)(o0 + d) = v0;
            *(__half2*)(o1 + d) = v1;
        }
    }
}

// ---------------- O-projection GEMM: fp32 out + bias ---------------------------
__global__ void __launch_bounds__(256) gemm_f16(const __half* __restrict__ A,
        const __half* __restrict__ Bw, const float* __restrict__ bias,
        float* __restrict__ C) {
    extern __shared__ char dsm[];
    int tid = threadIdx.x;
    int wid = tid >> 5, lane = tid & 31;
    int row0 = blockIdx.y * 128;
    int col0 = blockIdx.x * 128;
    int m0 = (wid & 3) * 32;
    int n0 = (wid >> 2) * 64;

    float acc[2][8][4];
    gemm_mainloop(dsm, A + (size_t)row0 * GK, Bw + (size_t)col0 * GK,
                  tid, lane, m0, n0, acc);

    int g = lane >> 2;
    int cl = (lane & 3) * 2;
#pragma unroll
    for (int mi = 0; mi < 2; mi++) {
#pragma unroll
        for (int nt = 0; nt < 8; nt++) {
            int gcol = col0 + n0 + nt * 8 + cl;
            float b0 = bias[gcol], b1 = bias[gcol + 1];
            int r0 = row0 + m0 + mi * 16 + g;
            float2 v0 = make_float2(acc[mi][nt][0] + b0, acc[mi][nt][1] + b1);
            float2 v1 = make_float2(acc[mi][nt][2] + b0, acc[mi][nt][3] + b1);
            *(float2*)(C + (size_t)r0 * CDIM + gcol) = v0;
            *(float2*)(C + (size_t)(r0 + 8) * CDIM + gcol) = v1;
        }
    }
}

// ---------------- fused mask: dtype detection + attend mask -------------------
__global__ void fused_mask(const void* __restrict__ pm) {
    __shared__ int okf, oki;
    int j = threadIdx.x;
    int w = blockIdx.x;
    if (j == 0) { okf = 1; oki = 1; }
    __syncthreads();
    const unsigned int* m32 = (const unsigned int*)pm;
    for (int i = j; i < 4096; i += 512) {
        unsigned int v = m32[i];
        if (v != 0u && v != 0x3f800000u) okf = 0;
        if (v > 1u) oki = 0;
    }
    __syncthreads();
    int mm = okf ? 2 : (oki ? 1 : 0);

    int b = w >> 5;
    int wi = w & 31;
    int p = wi * WINSZ - 128 + j;
    int attend = 1;
    if ((unsigned)p < (unsigned)T_LEN) {
        size_t im = (size_t)b * T_LEN + p;
        int v;
        if (mm == 0)      v = ((const unsigned char*)pm)[im] != 0;
        else if (mm == 1) v = ((const int*)pm)[im] != 0;
        else              v = ((const float*)pm)[im] != 0.0f;
        attend = !v;
    }
    __shared__ int allb;
    if (j == 0) allb = 1;
    __syncthreads();
    if (!attend) allb = 0;
    __syncthreads();
    if (j == 0 && allb) attend = 0;
    g_attend[w * 512 + j] = (unsigned char)attend;
}

// ---------------- tensor-core windowed attention (128-row CTA, 2 CTAs/SM) -----
// smem: Q 16KB | stage0 16KB (K 8K, V 8K) | stage1 16KB | bias
#define ATT_STG 16384
#define ATT_BIAS 49152
#define SMEM_ATTN (1024 + 49152 + 256)
#define LOG2E8 0.18033688011112042f    // 0.125 * log2(e)

__device__ __forceinline__ void load_kv_chunk(uint32_t stg, const __half* KH,
        const __half* VH, int b, int h, int p0, int tid) {
#pragma unroll
    for (int i = 0; i < 2; i++) {
        int f = tid + i * 256;
        int r = f >> 3, seg = f & 7;
        int p = p0 + r;
        uint32_t ok = ((unsigned)p < (unsigned)T_LEN) ? 16u : 0u;
        int pc = (p < 0) ? 0 : ((p >= T_LEN) ? (T_LEN - 1) : p);
        const __half* kk = KH + (((size_t)(b * T_LEN + pc) * NHEAD + h) << 6) + seg * 8;
        const __half* vv = VH + (((size_t)(b * T_LEN + pc) * NHEAD + h) << 6) + seg * 8;
        uint32_t sw = (uint32_t)r * 128 + (uint32_t)(((seg ^ (r & 7)) << 4));
        cp16z(stg + sw, kk, ok);
        cp16z(stg + 8192 + sw, vv, ok);
    }
}

__global__ void __launch_bounds__(256, 2) attn_mma(
        const __half* __restrict__ QH, const __half* __restrict__ KH,
        const __half* __restrict__ VH, __half* __restrict__ AO) {
    extern __shared__ char sm[];
    char* smA = (char*)(((uintptr_t)sm + 1023) & ~(uintptr_t)1023);
    uint32_t sb = smem_u32(smA);
    float* biasP = (float*)(smA + ATT_BIAS);

    int h = blockIdx.x;
    int wy = blockIdx.y;
    int w = wy >> 1, half = wy & 1;     // window, half-window
    int b = w >> 5, wi = w & 31;
    int tid = threadIdx.x, wid = tid >> 5, lane = tid & 31;
    int w0 = wid * 16;                  // warp's q-row offset within 128-row tile
    int qbase = wi * 256 + half * 128;  // CTA's first q row in sequence

    int rA = (lane & 7) + ((lane >> 3) & 1) * 8;
    int ksegA = lane >> 4;
    int rB = (lane & 7) + ((lane >> 4) << 3);
    int ksegB = (lane >> 3) & 1;
    int krV = (lane & 7) + ((lane >> 4) << 3);
    int nsegV = (lane >> 3) & 1;

    // Q tile: 128 rows x 128B
#pragma unroll
    for (int i = 0; i < 4; i++) {
        int f = tid + i * 256;                      // 0..1023
        int r = f >> 3, seg = f & 7;
        const __half* q = QH + (((size_t)(b * T_LEN + qbase + r) * NHEAD + h) << 6)
                          + seg * 8;
        uint32_t sw = (uint32_t)r * 128 + (uint32_t)(((seg ^ (r & 7)) << 4));
        cp16(sb + sw, q);
    }
    load_kv_chunk(sb + ATT_STG, KH, VH, b, h, wi * 256 - 128, tid);
    cp_commit();
    load_kv_chunk(sb + ATT_STG + 16384, KH, VH, b, h, wi * 256 - 64, tid);
    cp_commit();

    float O[8][4];
#pragma unroll
    for (int nt = 0; nt < 8; nt++)
#pragma unroll
        for (int j = 0; j < 4; j++) O[nt][j] = 0.0f;
    float lrow[2] = {0.f, 0.f};

    for (int c = 0; c < 8; c++) {
        if (c < 6) { cp_wait<1>(); } else { cp_wait<0>(); }
        if (tid < 64)
            biasP[tid] = g_attend[w * 512 + c * 64 + tid] ? 0.0f : -30000.0f;
        __syncthreads();

        uint32_t stg = sb + ATT_STG + (uint32_t)(c & 1) * 16384u;

        // ---- S = Q K^T (16 q rows per warp)
        float S[8][4];
#pragma unroll
        for (int nt = 0; nt < 8; nt++)
#pragma unroll
            for (int j = 0; j < 4; j++) S[nt][j] = 0.0f;

#pragma unroll
        for (int step = 0; step < 4; step++) {
            uint32_t kb[4][4];
#pragma unroll
            for (int g = 0; g < 4; g++) {
                int row = g * 16 + rB;
                ldsm4(kb[g], stg + (uint32_t)row * 128
                      + (uint32_t)(((step * 2 + ksegB) ^ (row & 7)) << 4));
            }
            int rowQ = w0 + rA;
            uint32_t qf[4];
            ldsm4(qf, sb + (uint32_t)rowQ * 128
                  + (uint32_t)(((step * 2 + ksegA) ^ (rowQ & 7)) << 4));
#pragma unroll
            for (int nt = 0; nt < 8; nt++)
                mma16816h(S[nt], qf, kb[nt >> 1][(nt & 1) * 2],
                          kb[nt >> 1][(nt & 1) * 2 + 1]);
        }

        // ---- P = ex2(S*0.125*log2e + bias) in fp16x2
        float2 bias[8];
#pragma unroll
        for (int nt = 0; nt < 8; nt++)
            bias[nt] = *(float2*)&biasP[nt * 8 + 2 * (lane & 3)];
        uint32_t P[8][2];
#pragma unroll
        for (int nt = 0; nt < 8; nt++) {
            float t0 = fmaf(S[nt][0], LOG2E8, bias[nt].x);
            float t1 = fmaf(S[nt][1], LOG2E8, bias[nt].y);
            float t2 = fmaf(S[nt][2], LOG2E8, bias[nt].x);
            float t3 = fmaf(S[nt][3], LOG2E8, bias[nt].y);
            uint32_t p01 = ex2_f16x2(t0, t1);
            uint32_t p23 = ex2_f16x2(t2, t3);
            P[nt][0] = p01;
            P[nt][1] = p23;
            float2 fa = __half22float2(*(__half2*)&p01);
            float2 fb = __half22float2(*(__half2*)&p23);
            lrow[0] += fa.x + fa.y;
            lrow[1] += fb.x + fb.y;
        }

        // ---- O += P V
#pragma unroll
        for (int step = 0; step < 4; step++) {
            uint32_t ah[4];
#pragma unroll
            for (int t2 = 0; t2 < 2; t2++) {
                ah[t2 * 2]     = P[2 * step + t2][0];
                ah[t2 * 2 + 1] = P[2 * step + t2][1];
            }
            uint32_t vb[4][4];
#pragma unroll
            for (int g = 0; g < 4; g++) {
                int vrow = step * 16 + krV;
                int seg = g * 2 + nsegV;
                ldsm4t(vb[g], stg + 8192u + (uint32_t)vrow * 128
                       + (uint32_t)(((seg ^ (vrow & 7)) << 4)));
            }
#pragma unroll
            for (int nt = 0; nt < 8; nt++)
                mma16816h(O[nt], ah, vb[nt >> 1][nt & 1],
                          vb[nt >> 1][(nt & 1) + 2]);
        }

        __syncthreads();
        if (c + 2 < 8) {
            load_kv_chunk(sb + ATT_STG + (uint32_t)(c & 1) * 16384u, KH, VH, b, h,
                          wi * 256 - 128 + (c + 2) * 64, tid);
            cp_commit();
        }
    }

    // ---- normalize + store fp16
#pragma unroll
    for (int s = 0; s < 2; s++) {
        lrow[s] += __shfl_xor_sync(0xffffffffu, lrow[s], 1);
        lrow[s] += __shfl_xor_sync(0xffffffffu, lrow[s], 2);
        lrow[s] = 1.0f / lrow[s];
    }
    int rr = lane >> 2, cc = 2 * (lane & 3);
#pragma unroll
    for (int nt = 0; nt < 8; nt++) {
        int tok0 = b * T_LEN + qbase + w0 + rr;
        int col = h * 64 + nt * 8 + cc;
        float i0 = lrow[0], i1 = lrow[1];
        __half2 v0 = __floats2half2_rn(O[nt][0] * i0, O[nt][1] * i0);
        __half2 v1 = __floats2half2_rn(O[nt][2] * i1, O[nt][3] * i1);
        *(__half2*)(AO + (size_t)tok0 * CDIM + col) = v0;
        *(__half2*)(AO + (size_t)(tok0 + 8) * CDIM + col) = v1;
    }
}

// ---------------- launch --------------------------------------------------------
extern "C" void kernel_launch(void* const* d_in, const int* in_sizes, int n_in,
                              void* d_out, int out_size) {
    const float* x    = (const float*)d_in[0];
    const void*  pm   = d_in[1];
    const float* cosT = (const float*)d_in[2];
    const float* sinT = (const float*)d_in[3];
    const float* Wq   = (const float*)d_in[4];
    const float* bq   = (const float*)d_in[5];
    const float* Wk   = (const float*)d_in[6];
    const float* bk   = (const float*)d_in[7];
    const float* Wv   = (const float*)d_in[8];
    const float* bv   = (const float*)d_in[9];
    const float* Wo   = (const float*)d_in[10];
    const float* bo   = (const float*)d_in[11];
    float* out = (float*)d_out;

    __half *XH, *AOH, *WH, *QH, *KH, *VH;
    cudaGetSymbolAddress((void**)&XH, g_XH);
    cudaGetSymbolAddress((void**)&AOH, g_AOH);
    cudaGetSymbolAddress((void**)&WH, g_WH);
    cudaGetSymbolAddress((void**)&QH, g_QH);
    cudaGetSymbolAddress((void**)&KH, g_KH);
    cudaGetSymbolAddress((void**)&VH, g_VH);

    cudaFuncSetAttribute(gemm_qkv, cudaFuncAttributeMaxDynamicSharedMemorySize, SMEM_GEMM);
    cudaFuncSetAttribute(gemm_f16, cudaFuncAttributeMaxDynamicSharedMemorySize, SMEM_GEMM);
    cudaFuncSetAttribute(attn_mma, cudaFuncAttributeMaxDynamicSharedMemorySize, SMEM_ATTN);

    convert_all<<<16384 + 4096, 256>>>(x, Wq, Wk, Wv, Wo, XH, WH);
    fused_mask<<<NWIN_TOT, 512>>>(pm);

    dim3 gq(CDIM / 128, NTOK / 128, 3);
    gemm_qkv<<<gq, 256, SMEM_GEMM>>>(XH, WH, bq, bk, bv, cosT, sinT, QH, KH, VH);

    attn_mma<<<dim3(NHEAD, NWIN_TOT * 2), 256, SMEM_ATTN>>>(QH, KH, VH, AOH);

    dim3 gg(CDIM / 128, NTOK / 128);
    gemm_f16<<<gg, 256, SMEM_GEMM>>>(AOH, WH + 3 * (size_t)CDIM * CDIM, bo, out);
}